// round 3
// baseline (speedup 1.0000x reference)
#include <cuda_runtime.h>
#include <cuda_bf16.h>
#include <math.h>

// ---------------- problem constants ----------------
#define T_     2048
#define HID_   2560
#define H_     40
#define NOPE_  64
#define ROPE_  32
#define VDIM_  64
#define QLORA_ 768
#define KVLORA_ 256
#define DQK_   288          // KVLORA + ROPE
#define QDIM_  96           // NOPE + ROPE
#define EPS_   1e-5f

// ---------------- scratch (device globals; no cudaMalloc allowed) ----------
__device__ float g_qa   [(size_t)T_ * QLORA_];            // 2048x768
__device__ float g_q    [(size_t)T_ * H_ * QDIM_];        // 2048x3840
__device__ float g_lat  [(size_t)T_ * DQK_];              // 2048x288
__device__ float g_kin  [(size_t)T_ * DQK_];              // 2048x288  (v_in | k_pe_rot)
__device__ float g_qin  [(size_t)T_ * H_ * DQK_];         // 2048x40x288 (scaled)
__device__ float g_olat [(size_t)T_ * H_ * KVLORA_];      // 2048x40x256
__device__ float g_o    [(size_t)T_ * H_ * VDIM_];        // 2048x2560

// ---------------- generic tiled SGEMM (64x64x16), optional batch ----------
// C[M,N] = alpha * A[M,K] * B[K,N]; row-major with leading dims; batch via z.
__global__ void sgemm_kernel(const float* __restrict__ A, const float* __restrict__ B,
                             float* __restrict__ C,
                             int M, int N, int K, int lda, int ldb, int ldc,
                             long strideA, long strideB, long strideC, float alpha)
{
    A += (long)blockIdx.z * strideA;
    B += (long)blockIdx.z * strideB;
    C += (long)blockIdx.z * strideC;

    __shared__ __align__(16) float As[16][64];
    __shared__ __align__(16) float Bs[16][64];

    const int tid = threadIdx.x;           // 256 threads
    const int tx = tid & 15, ty = tid >> 4;
    const int m0 = blockIdx.y * 64, n0 = blockIdx.x * 64;

    float acc[4][4] = {};

    for (int k0 = 0; k0 < K; k0 += 16) {
        #pragma unroll
        for (int i = 0; i < 4; i++) {
            int idx = tid + i * 256;            // 0..1023, A tile 64x16
            int mm = idx >> 4, kk = idx & 15;
            int gm = m0 + mm, gk = k0 + kk;
            As[kk][mm] = (gm < M && gk < K) ? A[(long)gm * lda + gk] : 0.f;
        }
        #pragma unroll
        for (int i = 0; i < 4; i++) {
            int idx = tid + i * 256;            // B tile 16x64
            int kk = idx >> 6, nn = idx & 63;
            int gk = k0 + kk, gn = n0 + nn;
            Bs[kk][nn] = (gk < K && gn < N) ? B[(long)gk * ldb + gn] : 0.f;
        }
        __syncthreads();
        #pragma unroll
        for (int kk = 0; kk < 16; kk++) {
            float a[4], b[4];
            *(float4*)a = *(const float4*)&As[kk][ty * 4];
            *(float4*)b = *(const float4*)&Bs[kk][tx * 4];
            #pragma unroll
            for (int i = 0; i < 4; i++)
                #pragma unroll
                for (int j = 0; j < 4; j++)
                    acc[i][j] = fmaf(a[i], b[j], acc[i][j]);
        }
        __syncthreads();
    }

    #pragma unroll
    for (int i = 0; i < 4; i++) {
        int gm = m0 + ty * 4 + i;
        if (gm >= M) continue;
        #pragma unroll
        for (int j = 0; j < 4; j++) {
            int gn = n0 + tx * 4 + j;
            if (gn < N) C[(long)gm * ldc + gn] = alpha * acc[i][j];
        }
    }
}

// ---------------- RMSNorm: y[row, :cols] = x * rsqrt(mean(x^2)+eps) * g ----
__global__ void rms_kernel(const float* __restrict__ x, const float* __restrict__ g,
                           float* __restrict__ y, int cols, int ldx, int ldy)
{
    long row = blockIdx.x;
    const float* xr = x + row * ldx;
    float*       yr = y + row * ldy;

    float ss = 0.f;
    for (int c = threadIdx.x; c < cols; c += blockDim.x) {
        float v = xr[c];
        ss = fmaf(v, v, ss);
    }
    #pragma unroll
    for (int o = 16; o; o >>= 1) ss += __shfl_xor_sync(0xffffffff, ss, o);

    __shared__ float red[8];
    __shared__ float s_inv;
    int w = threadIdx.x >> 5;
    if ((threadIdx.x & 31) == 0) red[w] = ss;
    __syncthreads();
    if (threadIdx.x == 0) {
        float tot = 0.f;
        int nw = blockDim.x >> 5;
        for (int i = 0; i < nw; i++) tot += red[i];
        s_inv = rsqrtf(tot / (float)cols + EPS_);
    }
    __syncthreads();
    float inv = s_inv;
    for (int c = threadIdx.x; c < cols; c += blockDim.x)
        yr[c] = xr[c] * inv * g[c];
}

// ---------------- RoPE on k_pe: latent[:,256:288] -> k_in[:,256:288] -------
__global__ void rope_k_kernel(const int* __restrict__ pos,
                              const float* __restrict__ latent,
                              float* __restrict__ kin)
{
    int t = blockIdx.x;
    int j = threadIdx.x;                  // 0..15
    float p = (float)pos[t];
    float inv_freq = powf(10000.f, -(float)j / 16.f);
    float f = p * inv_freq;
    float c = cosf(f), s = sinf(f);
    float x1 = latent[(long)t * DQK_ + KVLORA_ + j];
    float x2 = latent[(long)t * DQK_ + KVLORA_ + 16 + j];
    kin[(long)t * DQK_ + KVLORA_ + j]      = x1 * c - x2 * s;
    kin[(long)t * DQK_ + KVLORA_ + 16 + j] = x2 * c + x1 * s;
}

// ---------------- RoPE on q_pe (scaled): q[:,h,64:96] -> q_in[:,h,256:288] -
__global__ void rope_q_kernel(const int* __restrict__ pos,
                              const float* __restrict__ q,
                              float* __restrict__ qin, float scale)
{
    int t = blockIdx.x;
    int h = threadIdx.x >> 4;             // 0..39
    int j = threadIdx.x & 15;             // 0..15
    float p = (float)pos[t];
    float inv_freq = powf(10000.f, -(float)j / 16.f);
    float f = p * inv_freq;
    float c = cosf(f), s = sinf(f);
    long qb = (long)t * (H_ * QDIM_) + h * QDIM_ + NOPE_;
    float x1 = q[qb + j];
    float x2 = q[qb + 16 + j];
    long ob = (long)t * (H_ * DQK_) + h * DQK_ + KVLORA_;
    qin[ob + j]      = (x1 * c - x2 * s) * scale;
    qin[ob + 16 + j] = (x2 * c + x1 * s) * scale;
}

// ---------------- Flash attention (fp32, online softmax) -------------------
// Per block: one head h, one query tile of 32 rows. K tile of 32 rows in smem;
// V is the first 256 cols of the SAME K tile (shared latent). Q pre-scaled.
#define BM_ 32
#define BN_ 32
#define SK_ 292                           // padded row stride for Q/K tiles

__global__ void attn_kernel(const float* __restrict__ qin,
                            const float* __restrict__ kin,
                            float* __restrict__ olat)
{
    extern __shared__ __align__(16) float sm[];
    float* Qs   = sm;                     // BM_*SK_
    float* Ks   = Qs + BM_ * SK_;         // BN_*SK_
    float* Ss   = Ks + BN_ * SK_;         // BM_*33
    float* mrow = Ss + BM_ * 33;          // BM_
    float* lrow = mrow + BM_;             // BM_
    float* crow = lrow + BM_;             // BM_

    const int h   = blockIdx.y;
    const int qt  = (int)gridDim.x - 1 - (int)blockIdx.x;  // long blocks first
    const int tid = threadIdx.x;          // 256 threads
    const int rg  = tid & 7;              // row group: rows {rg, rg+8, rg+16, rg+24}
    const int vg  = tid >> 3;             // v group: dims [vg*8, vg*8+8)

    // load Q tile once (float4)
    for (int idx = tid; idx < BM_ * (DQK_ / 4); idx += 256) {
        int r = idx / (DQK_ / 4), c = idx % (DQK_ / 4);
        ((float4*)&Qs[r * SK_])[c] =
            ((const float4*)&qin[(long)(qt * BM_ + r) * (H_ * DQK_) + h * DQK_])[c];
    }
    if (tid < BM_) { mrow[tid] = -INFINITY; lrow[tid] = 0.f; }
    float acc[4][8] = {};
    __syncthreads();

    for (int kt = 0; kt <= qt; kt++) {
        // load K tile (float4)
        for (int idx = tid; idx < BN_ * (DQK_ / 4); idx += 256) {
            int r = idx / (DQK_ / 4), c = idx % (DQK_ / 4);
            ((float4*)&Ks[r * SK_])[c] =
                ((const float4*)&kin[(long)(kt * BN_ + r) * DQK_])[c];
        }
        __syncthreads();

        // S = Q K^T : each thread computes a 2x2 micro-tile
        {
            int si = 2 * (tid >> 4);      // even rows 0..30
            int sj = 2 * (tid & 15);      // even cols 0..30
            const float* q0 = &Qs[si * SK_];
            const float* q1 = &Qs[(si + 1) * SK_];
            const float* k0 = &Ks[sj * SK_];
            const float* k1 = &Ks[(sj + 1) * SK_];
            float s00 = 0, s01 = 0, s10 = 0, s11 = 0;
            #pragma unroll 6
            for (int d = 0; d < DQK_; d += 4) {
                float4 a0 = *(const float4*)(q0 + d);
                float4 a1 = *(const float4*)(q1 + d);
                float4 b0 = *(const float4*)(k0 + d);
                float4 b1 = *(const float4*)(k1 + d);
                s00 += a0.x*b0.x + a0.y*b0.y + a0.z*b0.z + a0.w*b0.w;
                s01 += a0.x*b1.x + a0.y*b1.y + a0.z*b1.z + a0.w*b1.w;
                s10 += a1.x*b0.x + a1.y*b0.y + a1.z*b0.z + a1.w*b0.w;
                s11 += a1.x*b1.x + a1.y*b1.y + a1.z*b1.z + a1.w*b1.w;
            }
            if (kt == qt) {               // causal mask inside diagonal tile
                int qi = qt * BM_ + si, kj = kt * BN_ + sj;
                if (kj     > qi    ) s00 = -INFINITY;
                if (kj + 1 > qi    ) s01 = -INFINITY;
                if (kj     > qi + 1) s10 = -INFINITY;
                if (kj + 1 > qi + 1) s11 = -INFINITY;
            }
            Ss[si * 33 + sj]           = s00;
            Ss[si * 33 + sj + 1]       = s01;
            Ss[(si + 1) * 33 + sj]     = s10;
            Ss[(si + 1) * 33 + sj + 1] = s11;
        }
        __syncthreads();

        // online softmax per row (32 threads, one row each)
        if (tid < BM_) {
            int r = tid;
            float m_old = mrow[r];
            float mx = m_old;
            #pragma unroll
            for (int j = 0; j < BN_; j++) mx = fmaxf(mx, Ss[r * 33 + j]);
            float corr = expf(m_old - mx);
            float sum = 0.f;
            #pragma unroll
            for (int j = 0; j < BN_; j++) {
                float p = expf(Ss[r * 33 + j] - mx);
                Ss[r * 33 + j] = p;
                sum += p;
            }
            mrow[r] = mx;
            lrow[r] = lrow[r] * corr + sum;
            crow[r] = corr;
        }
        __syncthreads();

        // acc = acc*corr + P * V   (V = Ks[:, :256])
        #pragma unroll
        for (int rr = 0; rr < 4; rr++) {
            float corr = crow[rg + rr * 8];
            #pragma unroll
            for (int v = 0; v < 8; v++) acc[rr][v] *= corr;
        }
        #pragma unroll 4
        for (int j = 0; j < BN_; j++) {
            float4 kv0 = *(const float4*)&Ks[j * SK_ + vg * 8];
            float4 kv1 = *(const float4*)&Ks[j * SK_ + vg * 8 + 4];
            #pragma unroll
            for (int rr = 0; rr < 4; rr++) {
                float p = Ss[(rg + rr * 8) * 33 + j];
                acc[rr][0] = fmaf(p, kv0.x, acc[rr][0]);
                acc[rr][1] = fmaf(p, kv0.y, acc[rr][1]);
                acc[rr][2] = fmaf(p, kv0.z, acc[rr][2]);
                acc[rr][3] = fmaf(p, kv0.w, acc[rr][3]);
                acc[rr][4] = fmaf(p, kv1.x, acc[rr][4]);
                acc[rr][5] = fmaf(p, kv1.y, acc[rr][5]);
                acc[rr][6] = fmaf(p, kv1.z, acc[rr][6]);
                acc[rr][7] = fmaf(p, kv1.w, acc[rr][7]);
            }
        }
        __syncthreads();                  // Ks/Ss reused next iteration
    }

    // write o_lat, normalized by l
    #pragma unroll
    for (int rr = 0; rr < 4; rr++) {
        int r = rg + rr * 8;
        float invl = 1.f / lrow[r];
        long t = (long)qt * BM_ + r;
        float* dst = &olat[t * (H_ * KVLORA_) + h * KVLORA_ + vg * 8];
        #pragma unroll
        for (int v = 0; v < 8; v++) dst[v] = acc[rr][v] * invl;
    }
}

// ---------------- host launcher --------------------------------------------
static inline void launch_sgemm(const float* A, const float* B, float* C,
                                int M, int N, int K, int lda, int ldb, int ldc,
                                int batches, long sA, long sB, long sC, float alpha)
{
    dim3 grid((N + 63) / 64, (M + 63) / 64, batches);
    sgemm_kernel<<<grid, 256>>>(A, B, C, M, N, K, lda, ldb, ldc, sA, sB, sC, alpha);
}

extern "C" void kernel_launch(void* const* d_in, const int* in_sizes, int n_in,
                              void* d_out, int out_size)
{
    const int*   positions = (const int*)  d_in[0];
    const float* hidden    = (const float*)d_in[1];
    const float* w_qa      = (const float*)d_in[2];
    const float* gqa       = (const float*)d_in[3];
    const float* w_qb      = (const float*)d_in[4];
    const float* w_kva     = (const float*)d_in[5];
    const float* gkva      = (const float*)d_in[6];
    const float* w_kc      = (const float*)d_in[7];
    const float* w_vc      = (const float*)d_in[8];
    const float* w_o       = (const float*)d_in[9];
    float* out = (float*)d_out;

    float *qa, *q, *lat, *kin, *qin, *olat, *o;
    cudaGetSymbolAddress((void**)&qa,   g_qa);
    cudaGetSymbolAddress((void**)&q,    g_q);
    cudaGetSymbolAddress((void**)&lat,  g_lat);
    cudaGetSymbolAddress((void**)&kin,  g_kin);
    cudaGetSymbolAddress((void**)&qin,  g_qin);
    cudaGetSymbolAddress((void**)&olat, g_olat);
    cudaGetSymbolAddress((void**)&o,    g_o);

    const float scale = 1.0f / sqrtf((float)(NOPE_ + ROPE_));   // 96^-0.5

    // 1) qa = hidden @ w_qa                       [2048,768]
    launch_sgemm(hidden, w_qa, qa, T_, QLORA_, HID_, HID_, QLORA_, QLORA_, 1, 0, 0, 0, 1.f);
    // 2) qa = rms(qa, g_qa)  (in place)
    rms_kernel<<<T_, 256>>>(qa, gqa, qa, QLORA_, QLORA_, QLORA_);
    // 3) q = qa @ w_qb                            [2048,3840]
    launch_sgemm(qa, w_qb, q, T_, H_ * QDIM_, QLORA_, QLORA_, H_ * QDIM_, H_ * QDIM_, 1, 0, 0, 0, 1.f);
    // 4) latent = hidden @ w_kva                  [2048,288]
    launch_sgemm(hidden, w_kva, lat, T_, DQK_, HID_, HID_, DQK_, DQK_, 1, 0, 0, 0, 1.f);
    // 5) k_in[:, :256] = rms(latent[:, :256], g_kva)
    rms_kernel<<<T_, 256>>>(lat, gkva, kin, KVLORA_, DQK_, DQK_);
    // 6) k_in[:, 256:288] = rope(latent[:, 256:288])
    rope_k_kernel<<<T_, 16>>>(positions, lat, kin);
    // 7) q_in[:, h, :256] = scale * q_nope[:, h, :] @ w_kc[h]   (batched over 40 heads)
    launch_sgemm(q, w_kc, qin, T_, KVLORA_, NOPE_,
                 H_ * QDIM_, KVLORA_, H_ * DQK_,
                 H_, (long)QDIM_, (long)NOPE_ * KVLORA_, (long)DQK_, scale);
    // 8) q_in[:, h, 256:288] = scale * rope(q_pe)
    rope_q_kernel<<<T_, H_ * 16>>>(positions, q, qin, scale);
    // 9) flash attention -> o_lat [2048, 40, 256]
    {
        int smem = (BM_ * SK_ + BN_ * SK_ + BM_ * 33 + 3 * BM_) * (int)sizeof(float);
        cudaFuncSetAttribute(attn_kernel, cudaFuncAttributeMaxDynamicSharedMemorySize, smem);
        dim3 grid(T_ / BM_, H_);
        attn_kernel<<<grid, 256, smem>>>(qin, kin, olat);
    }
    // 10) o[:, h*64:(h+1)*64] = o_lat[:, h, :] @ w_vc[h]   (batched)
    launch_sgemm(olat, w_vc, o, T_, VDIM_, KVLORA_,
                 H_ * KVLORA_, VDIM_, H_ * VDIM_,
                 H_, (long)KVLORA_, (long)KVLORA_ * VDIM_, (long)VDIM_, 1.f);
    // 11) out = o @ w_o                           [2048,2560]
    launch_sgemm(o, w_o, out, T_, HID_, H_ * VDIM_, H_ * VDIM_, HID_, HID_, 1, 0, 0, 0, 1.f);
}

// round 4
// speedup vs baseline: 7.6994x; 7.6994x over previous
#include <cuda_runtime.h>
#include <cuda_fp16.h>
#include <math.h>
#include <stdint.h>

// ---------------- problem constants ----------------
#define T_     2048
#define HID_   2560
#define H_     40
#define NOPE_  64
#define ROPE_  32
#define VDIM_  64
#define QLORA_ 768
#define KVLORA_ 256
#define DQK_   288          // KVLORA + ROPE
#define QDIM_  96           // NOPE + ROPE
#define EPS_   1e-5f
#define LOG2E_ 1.4426950408889634f

// ---------------- device scratch (no cudaMalloc allowed) -------------------
__device__ __half g_hH   [(size_t)T_ * HID_];
__device__ __half g_wqaT [(size_t)QLORA_ * HID_];
__device__ __half g_wqbT [(size_t)H_ * QDIM_ * QLORA_];
__device__ __half g_wkvaT[(size_t)DQK_ * HID_];
__device__ __half g_wkcT [(size_t)H_ * KVLORA_ * NOPE_];
__device__ __half g_wvcT [(size_t)H_ * VDIM_ * KVLORA_];
__device__ __half g_woT  [(size_t)HID_ * H_ * VDIM_];
__device__ float  g_qaF  [(size_t)T_ * QLORA_];
__device__ __half g_qaH  [(size_t)T_ * QLORA_];
__device__ __half g_qH   [(size_t)T_ * H_ * QDIM_];
__device__ float  g_latF [(size_t)T_ * DQK_];
__device__ __half g_kinH [(size_t)T_ * DQK_];
__device__ __half g_qinH [(size_t)T_ * H_ * DQK_];
__device__ __half g_olatH[(size_t)T_ * H_ * KVLORA_];
__device__ __half g_oH   [(size_t)T_ * H_ * VDIM_];

// ---------------- mma / ldmatrix primitives --------------------------------
__device__ __forceinline__ uint32_t cvta_s(const void* p) {
    return (uint32_t)__cvta_generic_to_shared(p);
}
__device__ __forceinline__ void ldsm_x4(uint32_t (&r)[4], uint32_t a) {
    asm volatile("ldmatrix.sync.aligned.m8n8.x4.shared.b16 {%0,%1,%2,%3}, [%4];"
        : "=r"(r[0]), "=r"(r[1]), "=r"(r[2]), "=r"(r[3]) : "r"(a));
}
__device__ __forceinline__ void ldsm_x4_t(uint32_t (&r)[4], uint32_t a) {
    asm volatile("ldmatrix.sync.aligned.m8n8.x4.trans.shared.b16 {%0,%1,%2,%3}, [%4];"
        : "=r"(r[0]), "=r"(r[1]), "=r"(r[2]), "=r"(r[3]) : "r"(a));
}
__device__ __forceinline__ void mma16816(float (&c)[4], const uint32_t (&a)[4],
                                         uint32_t b0, uint32_t b1) {
    asm volatile(
        "mma.sync.aligned.m16n8k16.row.col.f32.f16.f16.f32 "
        "{%0,%1,%2,%3}, {%4,%5,%6,%7}, {%8,%9}, {%0,%1,%2,%3};"
        : "+f"(c[0]), "+f"(c[1]), "+f"(c[2]), "+f"(c[3])
        : "r"(a[0]), "r"(a[1]), "r"(a[2]), "r"(a[3]), "r"(b0), "r"(b1));
}
__device__ __forceinline__ void stC(float* p, float v)  { *p = v; }
__device__ __forceinline__ void stC(__half* p, float v) { *p = __float2half(v); }

// ---------------- fp32 -> fp16 convert --------------------------------------
__global__ void f2h_kernel(const float* __restrict__ x, __half* __restrict__ y, int n4) {
    int i = blockIdx.x * blockDim.x + threadIdx.x;
    if (i < n4) {
        float4 v = ((const float4*)x)[i];
        ((__half2*)y)[2 * i]     = __floats2half2_rn(v.x, v.y);
        ((__half2*)y)[2 * i + 1] = __floats2half2_rn(v.z, v.w);
    }
}

// ---------------- transpose + convert: out[c][r] = (half)in[r][c] -----------
__global__ void t2h_kernel(const float* __restrict__ in, __half* __restrict__ out,
                           int R, int C, long sIn, long sOut) {
    in  += (long)blockIdx.z * sIn;
    out += (long)blockIdx.z * sOut;
    __shared__ float tile[32][33];
    int c0 = blockIdx.x * 32, r0 = blockIdx.y * 32;
    int tx = threadIdx.x, ty = threadIdx.y;
    #pragma unroll
    for (int i = 0; i < 32; i += 8)
        tile[ty + i][tx] = in[(long)(r0 + ty + i) * C + c0 + tx];
    __syncthreads();
    #pragma unroll
    for (int i = 0; i < 32; i += 8)
        out[(long)(c0 + ty + i) * R + r0 + tx] = __float2half(tile[tx][ty + i]);
}

// ---------------- generic HGEMM: C = alpha * A(fp16) * B^T-layout(fp16) -----
// A row-major [M][K] (lda), B stored as [N][K] (ldb), C [M][N] (ldc, OutT).
// BM=128, BN=64, BK=32; 256 threads; requires M%128==0, K%32==0.
template <typename OutT>
__global__ __launch_bounds__(256)
void hgemm_kernel(const __half* __restrict__ A, const __half* __restrict__ B,
                  OutT* __restrict__ C,
                  int M, int N, int K, int lda, int ldb, int ldc,
                  long sA, long sB, long sC, float alpha)
{
    A += (long)blockIdx.z * sA;
    B += (long)blockIdx.z * sB;
    C += (long)blockIdx.z * sC;

    __shared__ __align__(16) __half As[2][128 * 40];
    __shared__ __align__(16) __half Bs[2][64 * 40];

    const int tid = threadIdx.x;
    const int lane = tid & 31, wid = tid >> 5;
    const int wm = wid & 3, wn = wid >> 2;
    const int m0 = blockIdx.y * 128, n0 = blockIdx.x * 64;
    const int arow = tid >> 2, ac8 = tid & 3;

    float acc[2][4][4] = {};
    uint4 ra0, ra1, rb;

    // prologue load (kt = 0)
    {
        const __half* Ab = A + (long)m0 * lda;
        ra0 = *(const uint4*)&Ab[(long)arow * lda + ac8 * 8];
        ra1 = *(const uint4*)&Ab[(long)(arow + 64) * lda + ac8 * 8];
        int n = n0 + arow;
        rb = (n < N) ? *(const uint4*)&B[(long)n * ldb + ac8 * 8]
                     : make_uint4(0, 0, 0, 0);
        *(uint4*)&As[0][arow * 40 + ac8 * 8]        = ra0;
        *(uint4*)&As[0][(arow + 64) * 40 + ac8 * 8] = ra1;
        *(uint4*)&Bs[0][arow * 40 + ac8 * 8]        = rb;
    }
    __syncthreads();

    const int nk = K >> 5;
    for (int kt = 0; kt < nk; kt++) {
        const int cur = kt & 1;
        if (kt + 1 < nk) {
            const __half* Ab = A + (long)m0 * lda + (kt + 1) * 32;
            ra0 = *(const uint4*)&Ab[(long)arow * lda + ac8 * 8];
            ra1 = *(const uint4*)&Ab[(long)(arow + 64) * lda + ac8 * 8];
            int n = n0 + arow;
            rb = (n < N) ? *(const uint4*)&B[(long)n * ldb + (kt + 1) * 32 + ac8 * 8]
                         : make_uint4(0, 0, 0, 0);
        }

        uint32_t aB = cvta_s(&As[cur][0]) +
                      ((wm * 32 + (lane & 15)) * 40 + ((lane >> 4) << 3)) * 2;
        uint32_t bB = cvta_s(&Bs[cur][0]) + ((wn * 32 + lane) * 40) * 2;
        #pragma unroll
        for (int ks = 0; ks < 2; ks++) {
            uint32_t Af0[4], Af1[4], B0[4], B1[4];
            ldsm_x4(Af0, aB + ks * 32);
            ldsm_x4(Af1, aB + ks * 32 + 16 * 40 * 2);
            ldsm_x4(B0, bB + ks * 32);
            ldsm_x4(B1, bB + ks * 32 + 16);
            #pragma unroll
            for (int nt = 0; nt < 4; nt++) {
                mma16816(acc[0][nt], Af0, B0[nt], B1[nt]);
                mma16816(acc[1][nt], Af1, B0[nt], B1[nt]);
            }
        }
        __syncthreads();
        if (kt + 1 < nk) {
            const int nxt = (kt + 1) & 1;
            *(uint4*)&As[nxt][arow * 40 + ac8 * 8]        = ra0;
            *(uint4*)&As[nxt][(arow + 64) * 40 + ac8 * 8] = ra1;
            *(uint4*)&Bs[nxt][arow * 40 + ac8 * 8]        = rb;
            __syncthreads();
        }
    }

    #pragma unroll
    for (int mt = 0; mt < 2; mt++) {
        int r = m0 + wm * 32 + mt * 16 + (lane >> 2);
        #pragma unroll
        for (int nt = 0; nt < 4; nt++) {
            int c = n0 + wn * 32 + nt * 8 + (lane & 3) * 2;
            if (c < N) {
                stC(&C[(long)r * ldc + c],       alpha * acc[mt][nt][0]);
                stC(&C[(long)(r + 8) * ldc + c], alpha * acc[mt][nt][2]);
            }
            if (c + 1 < N) {
                stC(&C[(long)r * ldc + c + 1],       alpha * acc[mt][nt][1]);
                stC(&C[(long)(r + 8) * ldc + c + 1], alpha * acc[mt][nt][3]);
            }
        }
    }
}

// ---------------- RMSNorm (f32 in, OutT out) --------------------------------
template <typename OutT>
__global__ void rms_kernel(const float* __restrict__ x, const float* __restrict__ g,
                           OutT* __restrict__ y, int cols, int ldx, int ldy)
{
    long row = blockIdx.x;
    const float* xr = x + row * ldx;
    OutT*        yr = y + row * ldy;

    float ss = 0.f;
    for (int c = threadIdx.x; c < cols; c += blockDim.x) {
        float v = xr[c];
        ss = fmaf(v, v, ss);
    }
    #pragma unroll
    for (int o = 16; o; o >>= 1) ss += __shfl_xor_sync(0xffffffffu, ss, o);

    __shared__ float red[8];
    __shared__ float s_inv;
    int w = threadIdx.x >> 5;
    if ((threadIdx.x & 31) == 0) red[w] = ss;
    __syncthreads();
    if (threadIdx.x == 0) {
        float tot = 0.f;
        int nw = blockDim.x >> 5;
        for (int i = 0; i < nw; i++) tot += red[i];
        s_inv = rsqrtf(tot / (float)cols + EPS_);
    }
    __syncthreads();
    float inv = s_inv;
    for (int c = threadIdx.x; c < cols; c += blockDim.x)
        stC(&yr[c], xr[c] * inv * g[c]);
}

// ---------------- RoPE k: latF[:,256:288] -> kinH[:,256:288] ----------------
__global__ void rope_k_kernel(const int* __restrict__ pos,
                              const float* __restrict__ lat,
                              __half* __restrict__ kin)
{
    int t = blockIdx.x;
    int j = threadIdx.x;                  // 0..15
    float p = (float)pos[t];
    float inv_freq = powf(10000.f, -(float)j / 16.f);
    float f = p * inv_freq;
    float c = cosf(f), s = sinf(f);
    float x1 = lat[(long)t * DQK_ + KVLORA_ + j];
    float x2 = lat[(long)t * DQK_ + KVLORA_ + 16 + j];
    kin[(long)t * DQK_ + KVLORA_ + j]      = __float2half(x1 * c - x2 * s);
    kin[(long)t * DQK_ + KVLORA_ + 16 + j] = __float2half(x2 * c + x1 * s);
}

// ---------------- RoPE q (scaled): qH[:,h,64:96] -> qinH[:,h,256:288] -------
__global__ void rope_q_kernel(const int* __restrict__ pos,
                              const __half* __restrict__ q,
                              __half* __restrict__ qin, float scale)
{
    int t = blockIdx.x;
    int h = threadIdx.x >> 4;             // 0..39
    int j = threadIdx.x & 15;             // 0..15
    float p = (float)pos[t];
    float inv_freq = powf(10000.f, -(float)j / 16.f);
    float f = p * inv_freq;
    float c = cosf(f), s = sinf(f);
    long qb = (long)t * (H_ * QDIM_) + h * QDIM_ + NOPE_;
    float x1 = __half2float(q[qb + j]);
    float x2 = __half2float(q[qb + 16 + j]);
    long ob = (long)t * (H_ * DQK_) + h * DQK_ + KVLORA_;
    qin[ob + j]      = __float2half((x1 * c - x2 * s) * scale);
    qin[ob + 16 + j] = __float2half((x2 * c + x1 * s) * scale);
}

// ---------------- Flash attention (fp16 mma, online softmax) ----------------
// Block: head h, 64 q rows. K tile 64x288 fp16 in smem; V = K[:, :256].
// 8 warps: S phase warp = 16 rows x 32 cols; PV phase warp = 16 rows x 128 v.
#define ATT_SMEM 103168

__global__ __launch_bounds__(256)
void attn_kernel(const __half* __restrict__ qin, const __half* __restrict__ kin,
                 __half* __restrict__ olat)
{
    extern __shared__ __align__(16) char smraw[];
    __half* Qh   = (__half*)smraw;                  // 64 x 296
    __half* Kh   = Qh + 64 * 296;                   // 64 x 296
    float*  Ss   = (float*)(smraw + 75776);         // 64 x 68
    __half* Ph   = (__half*)(smraw + 93184);        // 64 x 72
    float*  mrow = (float*)(smraw + 102400);
    float*  lrow = mrow + 64;
    float*  crow = lrow + 64;

    const int h   = blockIdx.y;
    const int qt  = (int)gridDim.x - 1 - (int)blockIdx.x;  // long work first
    const int tid = threadIdx.x;
    const int lane = tid & 31, wid = tid >> 5;
    const int wm = wid & 3, wn = wid >> 2;

    // load Q tile (64 rows x 288 halves), 9 uint4 per thread
    {
        const __half* src = qin + ((long)(qt * 64) * H_ + h) * DQK_;
        #pragma unroll
        for (int i = 0; i < 9; i++) {
            int idx = tid + i * 256;
            int r = idx / 36, c8 = idx % 36;
            *(uint4*)&Qh[r * 296 + c8 * 8] =
                *(const uint4*)&src[(long)r * (H_ * DQK_) + c8 * 8];
        }
    }
    if (tid < 64) { mrow[tid] = -INFINITY; lrow[tid] = 0.f; }

    float o[16][4];
    #pragma unroll
    for (int i = 0; i < 16; i++)
        #pragma unroll
        for (int j = 0; j < 4; j++) o[i][j] = 0.f;

    for (int kt = 0; kt <= qt; kt++) {
        __syncthreads();   // publish Qh/init; prior PV done with Kh/Ph

        // load K tile
        {
            const __half* src = kin + (long)(kt * 64) * DQK_;
            #pragma unroll
            for (int i = 0; i < 9; i++) {
                int idx = tid + i * 256;
                int r = idx / 36, c8 = idx % 36;
                *(uint4*)&Kh[r * 296 + c8 * 8] =
                    *(const uint4*)&src[(long)r * DQK_ + c8 * 8];
            }
        }
        __syncthreads();

        // S = Q K^T  (warp: 16 rows x 32 cols)
        float s[4][4] = {};
        {
            uint32_t aB = cvta_s(Qh) +
                          ((wm * 16 + (lane & 15)) * 296 + ((lane >> 4) << 3)) * 2;
            uint32_t bB = cvta_s(Kh) + ((wn * 32 + lane) * 296) * 2;
            #pragma unroll
            for (int kk = 0; kk < 18; kk++) {
                uint32_t A[4], B0[4], B1[4];
                ldsm_x4(A, aB + kk * 32);
                ldsm_x4(B0, bB + kk * 32);
                ldsm_x4(B1, bB + kk * 32 + 16);
                #pragma unroll
                for (int nt = 0; nt < 4; nt++) mma16816(s[nt], A, B0[nt], B1[nt]);
            }
        }
        // write S frags to smem
        {
            int r = wm * 16 + (lane >> 2);
            int cb = wn * 32 + (lane & 3) * 2;
            #pragma unroll
            for (int nt = 0; nt < 4; nt++) {
                int c = cb + nt * 8;
                Ss[r * 68 + c]           = s[nt][0];
                Ss[r * 68 + c + 1]       = s[nt][1];
                Ss[(r + 8) * 68 + c]     = s[nt][2];
                Ss[(r + 8) * 68 + c + 1] = s[nt][3];
            }
        }
        __syncthreads();

        // online softmax: 4 threads per row, 16 cols each
        {
            int row = tid >> 2, q4 = tid & 3;
            int qi = qt * 64 + row;
            int kb = kt * 64 + q4 * 16;
            float sv[16];
            float mx = -INFINITY;
            #pragma unroll
            for (int j = 0; j < 16; j++) {
                float v = Ss[row * 68 + q4 * 16 + j];
                sv[j] = (kb + j > qi) ? -INFINITY : v;
                mx = fmaxf(mx, sv[j]);
            }
            mx = fmaxf(mx, __shfl_xor_sync(0xffffffffu, mx, 1));
            mx = fmaxf(mx, __shfl_xor_sync(0xffffffffu, mx, 2));
            float mo = mrow[row];
            float mn = fmaxf(mo, mx);
            float corr = exp2f((mo - mn) * LOG2E_);
            float sum = 0.f;
            #pragma unroll
            for (int j = 0; j < 16; j++) {
                float p = exp2f((sv[j] - mn) * LOG2E_);
                sum += p;
                Ph[row * 72 + q4 * 16 + j] = __float2half(p);
            }
            sum += __shfl_xor_sync(0xffffffffu, sum, 1);
            sum += __shfl_xor_sync(0xffffffffu, sum, 2);
            if (q4 == 0) {
                mrow[row] = mn;
                lrow[row] = lrow[row] * corr + sum;
                crow[row] = corr;
            }
        }
        __syncthreads();

        // O = O*corr + P V   (warp: 16 rows x 128 v-dims; V^T via ldmatrix.trans)
        {
            int r = wm * 16 + (lane >> 2);
            float c0 = crow[r], c1 = crow[r + 8];
            #pragma unroll
            for (int nt = 0; nt < 16; nt++) {
                o[nt][0] *= c0; o[nt][1] *= c0;
                o[nt][2] *= c1; o[nt][3] *= c1;
            }
            uint32_t pB = cvta_s(Ph) +
                          ((wm * 16 + (lane & 15)) * 72 + ((lane >> 4) << 3)) * 2;
            uint32_t vB = cvta_s(Kh) +
                          ((lane & 15) * 296 + wn * 128 + ((lane >> 4) << 3)) * 2;
            #pragma unroll
            for (int ks = 0; ks < 4; ks++) {
                uint32_t A[4];
                ldsm_x4(A, pB + ks * 32);
                #pragma unroll
                for (int ntp = 0; ntp < 8; ntp++) {
                    uint32_t B[4];
                    ldsm_x4_t(B, vB + (ks * 16 * 296 + ntp * 16) * 2);
                    mma16816(o[2 * ntp],     A, B[0], B[1]);
                    mma16816(o[2 * ntp + 1], A, B[2], B[3]);
                }
            }
        }
    }

    // epilogue: normalize by l and store fp16
    {
        int r0 = wm * 16 + (lane >> 2);
        float il0 = 1.f / lrow[r0];
        float il1 = 1.f / lrow[r0 + 8];
        long t0 = (long)qt * 64 + r0;
        __half* d0 = olat + (t0 * H_ + h) * KVLORA_;
        __half* d1 = olat + ((t0 + 8) * H_ + h) * KVLORA_;
        #pragma unroll
        for (int nt = 0; nt < 16; nt++) {
            int c = wn * 128 + nt * 8 + (lane & 3) * 2;
            *(__half2*)&d0[c] = __floats2half2_rn(o[nt][0] * il0, o[nt][1] * il0);
            *(__half2*)&d1[c] = __floats2half2_rn(o[nt][2] * il1, o[nt][3] * il1);
        }
    }
}

// ---------------- host launchers --------------------------------------------
template <typename OutT>
static void launch_hgemm(const __half* A, const __half* B, OutT* C,
                         int M, int N, int K, int lda, int ldb, int ldc,
                         int batch, long sA, long sB, long sC, float alpha)
{
    dim3 grid((N + 63) / 64, M / 128, batch);
    hgemm_kernel<OutT><<<grid, 256>>>(A, B, C, M, N, K, lda, ldb, ldc, sA, sB, sC, alpha);
}

extern "C" void kernel_launch(void* const* d_in, const int* in_sizes, int n_in,
                              void* d_out, int out_size)
{
    const int*   positions = (const int*)  d_in[0];
    const float* hidden    = (const float*)d_in[1];
    const float* w_qa      = (const float*)d_in[2];
    const float* gqa       = (const float*)d_in[3];
    const float* w_qb      = (const float*)d_in[4];
    const float* w_kva     = (const float*)d_in[5];
    const float* gkva      = (const float*)d_in[6];
    const float* w_kc      = (const float*)d_in[7];
    const float* w_vc      = (const float*)d_in[8];
    const float* w_o       = (const float*)d_in[9];
    float* out = (float*)d_out;

    __half *hH, *wqaT, *wqbT, *wkvaT, *wkcT, *wvcT, *woT;
    __half *qaH, *qH, *kinH, *qinH, *olatH, *oH;
    float *qaF, *latF;
    cudaGetSymbolAddress((void**)&hH,    g_hH);
    cudaGetSymbolAddress((void**)&wqaT,  g_wqaT);
    cudaGetSymbolAddress((void**)&wqbT,  g_wqbT);
    cudaGetSymbolAddress((void**)&wkvaT, g_wkvaT);
    cudaGetSymbolAddress((void**)&wkcT,  g_wkcT);
    cudaGetSymbolAddress((void**)&wvcT,  g_wvcT);
    cudaGetSymbolAddress((void**)&woT,   g_woT);
    cudaGetSymbolAddress((void**)&qaF,   g_qaF);
    cudaGetSymbolAddress((void**)&qaH,   g_qaH);
    cudaGetSymbolAddress((void**)&qH,    g_qH);
    cudaGetSymbolAddress((void**)&latF,  g_latF);
    cudaGetSymbolAddress((void**)&kinH,  g_kinH);
    cudaGetSymbolAddress((void**)&qinH,  g_qinH);
    cudaGetSymbolAddress((void**)&olatH, g_olatH);
    cudaGetSymbolAddress((void**)&oH,    g_oH);

    const float scale = 1.0f / sqrtf((float)(NOPE_ + ROPE_));

    // --- convert inputs / weights to fp16 (transposed to [N][K]) ---
    {
        int n4 = T_ * HID_ / 4;
        f2h_kernel<<<(n4 + 255) / 256, 256>>>(hidden, hH, n4);
    }
    dim3 tb(32, 8);
    t2h_kernel<<<dim3(QLORA_ / 32, HID_ / 32, 1), tb>>>(w_qa, wqaT, HID_, QLORA_, 0, 0);
    t2h_kernel<<<dim3(H_ * QDIM_ / 32, QLORA_ / 32, 1), tb>>>(w_qb, wqbT, QLORA_, H_ * QDIM_, 0, 0);
    t2h_kernel<<<dim3(DQK_ / 32, HID_ / 32, 1), tb>>>(w_kva, wkvaT, HID_, DQK_, 0, 0);
    t2h_kernel<<<dim3(HID_ / 32, H_ * VDIM_ / 32, 1), tb>>>(w_o, woT, H_ * VDIM_, HID_, 0, 0);
    t2h_kernel<<<dim3(KVLORA_ / 32, NOPE_ / 32, H_), tb>>>(w_kc, wkcT, NOPE_, KVLORA_,
                 (long)NOPE_ * KVLORA_, (long)NOPE_ * KVLORA_);
    t2h_kernel<<<dim3(VDIM_ / 32, KVLORA_ / 32, H_), tb>>>(w_vc, wvcT, KVLORA_, VDIM_,
                 (long)KVLORA_ * VDIM_, (long)KVLORA_ * VDIM_);

    // 1) qaF = hidden @ w_qa
    launch_hgemm<float>(hH, wqaT, qaF, T_, QLORA_, HID_, HID_, HID_, QLORA_, 1, 0, 0, 0, 1.f);
    // 2) qaH = rms(qaF)
    rms_kernel<__half><<<T_, 256>>>(qaF, gqa, qaH, QLORA_, QLORA_, QLORA_);
    // 3) qH = qaH @ w_qb
    launch_hgemm<__half>(qaH, wqbT, qH, T_, H_ * QDIM_, QLORA_, QLORA_, QLORA_, H_ * QDIM_, 1, 0, 0, 0, 1.f);
    // 4) latF = hidden @ w_kva
    launch_hgemm<float>(hH, wkvaT, latF, T_, DQK_, HID_, HID_, HID_, DQK_, 1, 0, 0, 0, 1.f);
    // 5) kinH[:, :256] = rms(latF[:, :256])
    rms_kernel<__half><<<T_, 256>>>(latF, gkva, kinH, KVLORA_, DQK_, DQK_);
    // 6) kinH[:, 256:288] = rope(latF[:, 256:288])
    rope_k_kernel<<<T_, 16>>>(positions, latF, kinH);
    // 7) qinH[:, h, :256] = scale * q_nope @ w_kc[h]   (batched)
    launch_hgemm<__half>(qH, wkcT, qinH, T_, KVLORA_, NOPE_,
                         H_ * QDIM_, NOPE_, H_ * DQK_,
                         H_, (long)QDIM_, (long)NOPE_ * KVLORA_, (long)DQK_, scale);
    // 8) qinH[:, h, 256:288] = scale * rope(q_pe)
    rope_q_kernel<<<T_, H_ * 16>>>(positions, qH, qinH, scale);
    // 9) flash attention -> olatH
    {
        cudaFuncSetAttribute(attn_kernel, cudaFuncAttributeMaxDynamicSharedMemorySize, ATT_SMEM);
        dim3 grid(T_ / 64, H_);
        attn_kernel<<<grid, 256, ATT_SMEM>>>(qinH, kinH, olatH);
    }
    // 10) oH[:, h*64:] = olatH[:, h, :] @ w_vc[h]   (batched)
    launch_hgemm<__half>(olatH, wvcT, oH, T_, VDIM_, KVLORA_,
                         H_ * KVLORA_, KVLORA_, H_ * VDIM_,
                         H_, (long)KVLORA_, (long)KVLORA_ * VDIM_, (long)VDIM_, 1.f);
    // 11) out = oH @ w_o
    launch_hgemm<float>(oH, woT, out, T_, HID_, H_ * VDIM_, H_ * VDIM_, H_ * VDIM_, HID_, 1, 0, 0, 0, 1.f);
}

// round 5
// speedup vs baseline: 8.6419x; 1.1224x over previous
#include <cuda_runtime.h>
#include <cuda_fp16.h>
#include <math.h>
#include <stdint.h>

// ---------------- problem constants ----------------
#define T_     2048
#define HID_   2560
#define H_     40
#define NOPE_  64
#define ROPE_  32
#define VDIM_  64
#define QLORA_ 768
#define KVLORA_ 256
#define DQK_   288          // KVLORA + ROPE
#define QDIM_  96           // NOPE + ROPE
#define EPS_   1e-5f
#define LOG2E_ 1.4426950408889634f

// ---------------- device scratch (no cudaMalloc allowed) -------------------
__device__ __half g_hH   [(size_t)T_ * HID_];
__device__ __half g_wqaT [(size_t)QLORA_ * HID_];
__device__ __half g_wqbT [(size_t)H_ * QDIM_ * QLORA_];
__device__ __half g_wkvaT[(size_t)DQK_ * HID_];
__device__ __half g_wkcT [(size_t)H_ * KVLORA_ * NOPE_];
__device__ __half g_wvcT [(size_t)H_ * VDIM_ * KVLORA_];
__device__ __half g_woT  [(size_t)HID_ * H_ * VDIM_];
__device__ float  g_qaF  [(size_t)T_ * QLORA_];
__device__ __half g_qaH  [(size_t)T_ * QLORA_];
__device__ __half g_qH   [(size_t)T_ * H_ * QDIM_];
__device__ float  g_latF [(size_t)T_ * DQK_];
__device__ __half g_kinH [(size_t)T_ * DQK_];
__device__ __half g_qinH [(size_t)T_ * H_ * DQK_];
__device__ __half g_olatH[(size_t)T_ * H_ * KVLORA_];
__device__ __half g_oH   [(size_t)T_ * H_ * VDIM_];

// ---------------- mma / ldmatrix / cp.async primitives ---------------------
__device__ __forceinline__ uint32_t cvta_s(const void* p) {
    return (uint32_t)__cvta_generic_to_shared(p);
}
__device__ __forceinline__ void ldsm_x4(uint32_t (&r)[4], uint32_t a) {
    asm volatile("ldmatrix.sync.aligned.m8n8.x4.shared.b16 {%0,%1,%2,%3}, [%4];"
        : "=r"(r[0]), "=r"(r[1]), "=r"(r[2]), "=r"(r[3]) : "r"(a));
}
__device__ __forceinline__ void ldsm_x4_t(uint32_t (&r)[4], uint32_t a) {
    asm volatile("ldmatrix.sync.aligned.m8n8.x4.trans.shared.b16 {%0,%1,%2,%3}, [%4];"
        : "=r"(r[0]), "=r"(r[1]), "=r"(r[2]), "=r"(r[3]) : "r"(a));
}
__device__ __forceinline__ void mma16816(float (&c)[4], const uint32_t (&a)[4],
                                         uint32_t b0, uint32_t b1) {
    asm volatile(
        "mma.sync.aligned.m16n8k16.row.col.f32.f16.f16.f32 "
        "{%0,%1,%2,%3}, {%4,%5,%6,%7}, {%8,%9}, {%0,%1,%2,%3};"
        : "+f"(c[0]), "+f"(c[1]), "+f"(c[2]), "+f"(c[3])
        : "r"(a[0]), "r"(a[1]), "r"(a[2]), "r"(a[3]), "r"(b0), "r"(b1));
}
__device__ __forceinline__ void cpa16(uint32_t dst, const void* src) {
    asm volatile("cp.async.cg.shared.global [%0], [%1], 16;"
                 :: "r"(dst), "l"(src) : "memory");
}
__device__ __forceinline__ void cpa16z(uint32_t dst, const void* src, int sz) {
    asm volatile("cp.async.cg.shared.global [%0], [%1], 16, %2;"
                 :: "r"(dst), "l"(src), "r"(sz) : "memory");
}
__device__ __forceinline__ void cpa_commit() {
    asm volatile("cp.async.commit_group;" ::: "memory");
}
__device__ __forceinline__ void cpa_wait0() {
    asm volatile("cp.async.wait_group 0;" ::: "memory");
}
__device__ __forceinline__ void stC(float* p, float v)  { *p = v; }
__device__ __forceinline__ void stC(__half* p, float v) { *p = __float2half(v); }

// ---------------- fp32 -> fp16 convert --------------------------------------
__global__ void f2h_kernel(const float* __restrict__ x, __half* __restrict__ y, int n4) {
    int i = blockIdx.x * blockDim.x + threadIdx.x;
    if (i < n4) {
        float4 v = ((const float4*)x)[i];
        ((__half2*)y)[2 * i]     = __floats2half2_rn(v.x, v.y);
        ((__half2*)y)[2 * i + 1] = __floats2half2_rn(v.z, v.w);
    }
}

// ---------------- transpose + convert: out[c][r] = (half)in[r][c] -----------
__global__ void t2h_kernel(const float* __restrict__ in, __half* __restrict__ out,
                           int R, int C, long sIn, long sOut) {
    in  += (long)blockIdx.z * sIn;
    out += (long)blockIdx.z * sOut;
    __shared__ float tile[32][33];
    int c0 = blockIdx.x * 32, r0 = blockIdx.y * 32;
    int tx = threadIdx.x, ty = threadIdx.y;
    #pragma unroll
    for (int i = 0; i < 32; i += 8)
        tile[ty + i][tx] = in[(long)(r0 + ty + i) * C + c0 + tx];
    __syncthreads();
    #pragma unroll
    for (int i = 0; i < 32; i += 8)
        out[(long)(c0 + ty + i) * R + r0 + tx] = __float2half(tile[tx][ty + i]);
}

// ---------------- generic HGEMM, cp.async 2-stage ---------------------------
// A row-major [M][K] (lda), B stored as [N][K] (ldb), C [M][N] (ldc, OutT).
// BM=128, BN=64, BK=32; 256 threads; M%128==0, K%32==0.
template <typename OutT>
__global__ __launch_bounds__(256)
void hgemm_kernel(const __half* __restrict__ A, const __half* __restrict__ B,
                  OutT* __restrict__ C,
                  int M, int N, int K, int lda, int ldb, int ldc,
                  long sA, long sB, long sC, float alpha)
{
    A += (long)blockIdx.z * sA;
    B += (long)blockIdx.z * sB;
    C += (long)blockIdx.z * sC;

    __shared__ __align__(16) __half As[2][128 * 40];
    __shared__ __align__(16) __half Bs[2][64 * 40];

    const int tid = threadIdx.x;
    const int lane = tid & 31, wid = tid >> 5;
    const int wm = wid & 3, wn = wid >> 2;
    const int m0 = blockIdx.y * 128, n0 = blockIdx.x * 64;

    float acc[2][4][4] = {};

    auto issue = [&](int st, int kt) {
        #pragma unroll
        for (int i = 0; i < 2; i++) {
            int id = tid + i * 256;
            int rr = id >> 2, cc = id & 3;
            cpa16(cvta_s(&As[st][rr * 40 + cc * 8]),
                  A + (long)(m0 + rr) * lda + kt * 32 + cc * 8);
        }
        {
            int rr = tid >> 2, cc = tid & 3;
            bool ok = (n0 + rr) < N;
            const __half* src = ok ? (B + (long)(n0 + rr) * ldb + kt * 32 + cc * 8) : B;
            cpa16z(cvta_s(&Bs[st][rr * 40 + cc * 8]), src, ok ? 16 : 0);
        }
        cpa_commit();
    };

    issue(0, 0);
    const int nk = K >> 5;
    for (int kt = 0; kt < nk; kt++) {
        const int cur = kt & 1;
        cpa_wait0();
        __syncthreads();
        if (kt + 1 < nk) issue(cur ^ 1, kt + 1);

        uint32_t aB = cvta_s(&As[cur][0]) +
                      ((wm * 32 + (lane & 15)) * 40 + ((lane >> 4) << 3)) * 2;
        uint32_t bB = cvta_s(&Bs[cur][0]) + ((wn * 32 + lane) * 40) * 2;
        #pragma unroll
        for (int ks = 0; ks < 2; ks++) {
            uint32_t Af0[4], Af1[4], B0[4], B1[4];
            ldsm_x4(Af0, aB + ks * 32);
            ldsm_x4(Af1, aB + ks * 32 + 16 * 40 * 2);
            ldsm_x4(B0, bB + ks * 32);
            ldsm_x4(B1, bB + ks * 32 + 16);
            #pragma unroll
            for (int nt = 0; nt < 4; nt++) {
                mma16816(acc[0][nt], Af0, B0[nt], B1[nt]);
                mma16816(acc[1][nt], Af1, B0[nt], B1[nt]);
            }
        }
    }

    #pragma unroll
    for (int mt = 0; mt < 2; mt++) {
        int r = m0 + wm * 32 + mt * 16 + (lane >> 2);
        #pragma unroll
        for (int nt = 0; nt < 4; nt++) {
            int c = n0 + wn * 32 + nt * 8 + (lane & 3) * 2;
            if (c < N) {
                stC(&C[(long)r * ldc + c],       alpha * acc[mt][nt][0]);
                stC(&C[(long)(r + 8) * ldc + c], alpha * acc[mt][nt][2]);
            }
            if (c + 1 < N) {
                stC(&C[(long)r * ldc + c + 1],       alpha * acc[mt][nt][1]);
                stC(&C[(long)(r + 8) * ldc + c + 1], alpha * acc[mt][nt][3]);
            }
        }
    }
}

// ---------------- RMSNorm (f32 in, OutT out) --------------------------------
template <typename OutT>
__global__ void rms_kernel(const float* __restrict__ x, const float* __restrict__ g,
                           OutT* __restrict__ y, int cols, int ldx, int ldy)
{
    long row = blockIdx.x;
    const float* xr = x + row * ldx;
    OutT*        yr = y + row * ldy;

    float ss = 0.f;
    for (int c = threadIdx.x; c < cols; c += blockDim.x) {
        float v = xr[c];
        ss = fmaf(v, v, ss);
    }
    #pragma unroll
    for (int o = 16; o; o >>= 1) ss += __shfl_xor_sync(0xffffffffu, ss, o);

    __shared__ float red[8];
    __shared__ float s_inv;
    int w = threadIdx.x >> 5;
    if ((threadIdx.x & 31) == 0) red[w] = ss;
    __syncthreads();
    if (threadIdx.x == 0) {
        float tot = 0.f;
        int nw = blockDim.x >> 5;
        for (int i = 0; i < nw; i++) tot += red[i];
        s_inv = rsqrtf(tot / (float)cols + EPS_);
    }
    __syncthreads();
    float inv = s_inv;
    for (int c = threadIdx.x; c < cols; c += blockDim.x)
        stC(&yr[c], xr[c] * inv * g[c]);
}

// ---------------- RoPE k: latF[:,256:288] -> kinH[:,256:288] ----------------
__global__ void rope_k_kernel(const int* __restrict__ pos,
                              const float* __restrict__ lat,
                              __half* __restrict__ kin)
{
    int t = blockIdx.x;
    int j = threadIdx.x;                  // 0..15
    float p = (float)pos[t];
    float inv_freq = powf(10000.f, -(float)j / 16.f);
    float f = p * inv_freq;
    float c = cosf(f), s = sinf(f);
    float x1 = lat[(long)t * DQK_ + KVLORA_ + j];
    float x2 = lat[(long)t * DQK_ + KVLORA_ + 16 + j];
    kin[(long)t * DQK_ + KVLORA_ + j]      = __float2half(x1 * c - x2 * s);
    kin[(long)t * DQK_ + KVLORA_ + 16 + j] = __float2half(x2 * c + x1 * s);
}

// ---------------- RoPE q (scaled): qH[:,h,64:96] -> qinH[:,h,256:288] -------
__global__ void rope_q_kernel(const int* __restrict__ pos,
                              const __half* __restrict__ q,
                              __half* __restrict__ qin, float scale)
{
    int t = blockIdx.x;
    int h = threadIdx.x >> 4;             // 0..39
    int j = threadIdx.x & 15;             // 0..15
    float p = (float)pos[t];
    float inv_freq = powf(10000.f, -(float)j / 16.f);
    float f = p * inv_freq;
    float c = cosf(f), s = sinf(f);
    long qb = (long)t * (H_ * QDIM_) + h * QDIM_ + NOPE_;
    float x1 = __half2float(q[qb + j]);
    float x2 = __half2float(q[qb + 16 + j]);
    long ob = (long)t * (H_ * DQK_) + h * DQK_ + KVLORA_;
    qin[ob + j]      = __float2half((x1 * c - x2 * s) * scale);
    qin[ob + 16 + j] = __float2half((x2 * c + x1 * s) * scale);
}

// ---------------- Flash attention (fp16 mma, register softmax) --------------
// Block: head h, 64 q rows. K tile 64x288 fp16 in smem; V = K[:, :256].
// 8 warps: S warp tile 16x32; PV warp tile 16x128. 2 CTAs/SM.
#define ATT_SMEM 86528

__global__ __launch_bounds__(256, 2)
void attn_kernel(const __half* __restrict__ qin, const __half* __restrict__ kin,
                 __half* __restrict__ olat)
{
    extern __shared__ __align__(16) char smraw[];
    __half* Qh   = (__half*)smraw;                  // 64 x 296       (37888 B)
    __half* Kh   = Qh + 64 * 296;                   // 64 x 296       (37888 B)
    __half* Ph   = (__half*)(smraw + 75776);        // 64 x 72        ( 9216 B)
    float*  mrow = (float*)(smraw + 84992);         // 64
    float*  lrow = (float*)(smraw + 85248);         // 64
    float*  pm   = (float*)(smraw + 85504);         // 2 x 64
    float*  ps   = (float*)(smraw + 86016);         // 2 x 64

    const int h    = blockIdx.y;
    const int qt   = (int)gridDim.x - 1 - (int)blockIdx.x;  // long work first
    const int tid  = threadIdx.x;
    const int lane = tid & 31, wid = tid >> 5;
    const int wm = wid & 3, wn = wid >> 2;
    const int r  = wm * 16 + (lane >> 2);           // tile row (and r+8)

    // async Q tile load: 64 rows x 288 halves, 16B chunks, 9 per thread
    {
        const __half* src = qin + ((long)(qt * 64) * H_ + h) * DQK_;
        #pragma unroll
        for (int i = 0; i < 9; i++) {
            int idx = tid + i * 256;
            int rr = idx / 36, cc = idx % 36;
            cpa16(cvta_s(&Qh[rr * 296 + cc * 8]),
                  src + (long)rr * (H_ * DQK_) + cc * 8);
        }
        cpa_commit();
    }
    if (tid < 64) { mrow[tid] = -INFINITY; lrow[tid] = 0.f; }

    float o[16][4];
    #pragma unroll
    for (int i = 0; i < 16; i++)
        #pragma unroll
        for (int j = 0; j < 4; j++) o[i][j] = 0.f;

    for (int kt = 0; kt <= qt; kt++) {
        __syncthreads();   // prior PV done with Kh/Ph; mrow/lrow init visible

        // async K tile load
        {
            const __half* src = kin + (long)(kt * 64) * DQK_;
            #pragma unroll
            for (int i = 0; i < 9; i++) {
                int idx = tid + i * 256;
                int rr = idx / 36, cc = idx % 36;
                cpa16(cvta_s(&Kh[rr * 296 + cc * 8]),
                      src + (long)rr * DQK_ + cc * 8);
            }
            cpa_commit();
        }
        cpa_wait0();
        __syncthreads();

        // ---- S = Q K^T  (warp: 16 rows x 32 cols) ----
        float s[4][4] = {};
        {
            uint32_t aB = cvta_s(Qh) +
                          ((wm * 16 + (lane & 15)) * 296 + ((lane >> 4) << 3)) * 2;
            uint32_t bB = cvta_s(Kh) + ((wn * 32 + lane) * 296) * 2;
            #pragma unroll
            for (int kk = 0; kk < 18; kk++) {
                uint32_t Af[4], B0[4], B1[4];
                ldsm_x4(Af, aB + kk * 32);
                ldsm_x4(B0, bB + kk * 32);
                ldsm_x4(B1, bB + kk * 32 + 16);
                #pragma unroll
                for (int nt = 0; nt < 4; nt++) mma16816(s[nt], Af, B0[nt], B1[nt]);
            }
        }

        // ---- causal mask (diagonal tile) in registers ----
        if (kt == qt) {
            int rg = r;                         // same-tile comparison
            int cg = wn * 32 + (lane & 3) * 2;
            #pragma unroll
            for (int nt = 0; nt < 4; nt++) {
                int c = cg + nt * 8;
                if (c     > rg)     s[nt][0] = -INFINITY;
                if (c + 1 > rg)     s[nt][1] = -INFINITY;
                if (c     > rg + 8) s[nt][2] = -INFINITY;
                if (c + 1 > rg + 8) s[nt][3] = -INFINITY;
            }
        }

        // ---- phase A: warp-local row max, publish partials ----
        float mx0 = -INFINITY, mx1 = -INFINITY;
        #pragma unroll
        for (int nt = 0; nt < 4; nt++) {
            mx0 = fmaxf(mx0, fmaxf(s[nt][0], s[nt][1]));
            mx1 = fmaxf(mx1, fmaxf(s[nt][2], s[nt][3]));
        }
        mx0 = fmaxf(mx0, __shfl_xor_sync(0xffffffffu, mx0, 1));
        mx0 = fmaxf(mx0, __shfl_xor_sync(0xffffffffu, mx0, 2));
        mx1 = fmaxf(mx1, __shfl_xor_sync(0xffffffffu, mx1, 1));
        mx1 = fmaxf(mx1, __shfl_xor_sync(0xffffffffu, mx1, 2));
        float mo0 = mrow[r], mo1 = mrow[r + 8];
        if ((lane & 3) == 0) {
            pm[wn * 64 + r]     = mx0;
            pm[wn * 64 + r + 8] = mx1;
        }
        __syncthreads();

        // ---- phase B: combined max, exp in regs, write P (half2), sums ----
        float mn0 = fmaxf(mo0, fmaxf(pm[r],     pm[64 + r]));
        float mn1 = fmaxf(mo1, fmaxf(pm[r + 8], pm[64 + r + 8]));
        float corr0 = exp2f((mo0 - mn0) * LOG2E_);
        float corr1 = exp2f((mo1 - mn1) * LOG2E_);
        float sum0 = 0.f, sum1 = 0.f;
        {
            int cb = wn * 32 + (lane & 3) * 2;
            #pragma unroll
            for (int nt = 0; nt < 4; nt++) {
                float p0 = exp2f((s[nt][0] - mn0) * LOG2E_);
                float p1 = exp2f((s[nt][1] - mn0) * LOG2E_);
                float p2 = exp2f((s[nt][2] - mn1) * LOG2E_);
                float p3 = exp2f((s[nt][3] - mn1) * LOG2E_);
                sum0 += p0 + p1;
                sum1 += p2 + p3;
                *(__half2*)&Ph[r * 72 + cb + nt * 8]       = __floats2half2_rn(p0, p1);
                *(__half2*)&Ph[(r + 8) * 72 + cb + nt * 8] = __floats2half2_rn(p2, p3);
            }
        }
        sum0 += __shfl_xor_sync(0xffffffffu, sum0, 1);
        sum0 += __shfl_xor_sync(0xffffffffu, sum0, 2);
        sum1 += __shfl_xor_sync(0xffffffffu, sum1, 1);
        sum1 += __shfl_xor_sync(0xffffffffu, sum1, 2);
        if ((lane & 3) == 0) {
            ps[wn * 64 + r]     = sum0;
            ps[wn * 64 + r + 8] = sum1;
            if (wn == 0) { mrow[r] = mn0; mrow[r + 8] = mn1; }
        }
        __syncthreads();

        // ---- PV: O = O*corr + P V  (V = Kh[:, :256] via ldmatrix.trans) ----
        if (wn == 0 && (lane & 3) == 0) {
            lrow[r]     = lrow[r]     * corr0 + ps[r]     + ps[64 + r];
            lrow[r + 8] = lrow[r + 8] * corr1 + ps[r + 8] + ps[64 + r + 8];
        }
        #pragma unroll
        for (int nt = 0; nt < 16; nt++) {
            o[nt][0] *= corr0; o[nt][1] *= corr0;
            o[nt][2] *= corr1; o[nt][3] *= corr1;
        }
        {
            uint32_t pB = cvta_s(Ph) +
                          ((wm * 16 + (lane & 15)) * 72 + ((lane >> 4) << 3)) * 2;
            uint32_t vB = cvta_s(Kh) +
                          ((lane & 15) * 296 + wn * 128 + ((lane >> 4) << 3)) * 2;
            #pragma unroll
            for (int ks = 0; ks < 4; ks++) {
                uint32_t Af[4];
                ldsm_x4(Af, pB + ks * 32);
                #pragma unroll
                for (int ntp = 0; ntp < 8; ntp++) {
                    uint32_t B[4];
                    ldsm_x4_t(B, vB + (ks * 16 * 296 + ntp * 16) * 2);
                    mma16816(o[2 * ntp],     Af, B[0], B[1]);
                    mma16816(o[2 * ntp + 1], Af, B[2], B[3]);
                }
            }
        }
    }

    __syncthreads();   // final lrow updates visible

    // epilogue: normalize by l and store fp16
    {
        float il0 = 1.f / lrow[r];
        float il1 = 1.f / lrow[r + 8];
        long t0 = (long)qt * 64 + r;
        __half* d0 = olat + (t0 * H_ + h) * KVLORA_;
        __half* d1 = olat + ((t0 + 8) * H_ + h) * KVLORA_;
        #pragma unroll
        for (int nt = 0; nt < 16; nt++) {
            int c = wn * 128 + nt * 8 + (lane & 3) * 2;
            *(__half2*)&d0[c] = __floats2half2_rn(o[nt][0] * il0, o[nt][1] * il0);
            *(__half2*)&d1[c] = __floats2half2_rn(o[nt][2] * il1, o[nt][3] * il1);
        }
    }
}

// ---------------- host launchers --------------------------------------------
template <typename OutT>
static void launch_hgemm(const __half* A, const __half* B, OutT* C,
                         int M, int N, int K, int lda, int ldb, int ldc,
                         int batch, long sA, long sB, long sC, float alpha)
{
    dim3 grid((N + 63) / 64, M / 128, batch);
    hgemm_kernel<OutT><<<grid, 256>>>(A, B, C, M, N, K, lda, ldb, ldc, sA, sB, sC, alpha);
}

extern "C" void kernel_launch(void* const* d_in, const int* in_sizes, int n_in,
                              void* d_out, int out_size)
{
    const int*   positions = (const int*)  d_in[0];
    const float* hidden    = (const float*)d_in[1];
    const float* w_qa      = (const float*)d_in[2];
    const float* gqa       = (const float*)d_in[3];
    const float* w_qb      = (const float*)d_in[4];
    const float* w_kva     = (const float*)d_in[5];
    const float* gkva      = (const float*)d_in[6];
    const float* w_kc      = (const float*)d_in[7];
    const float* w_vc      = (const float*)d_in[8];
    const float* w_o       = (const float*)d_in[9];
    float* out = (float*)d_out;

    __half *hH, *wqaT, *wqbT, *wkvaT, *wkcT, *wvcT, *woT;
    __half *qaH, *qH, *kinH, *qinH, *olatH, *oH;
    float *qaF, *latF;
    cudaGetSymbolAddress((void**)&hH,    g_hH);
    cudaGetSymbolAddress((void**)&wqaT,  g_wqaT);
    cudaGetSymbolAddress((void**)&wqbT,  g_wqbT);
    cudaGetSymbolAddress((void**)&wkvaT, g_wkvaT);
    cudaGetSymbolAddress((void**)&wkcT,  g_wkcT);
    cudaGetSymbolAddress((void**)&wvcT,  g_wvcT);
    cudaGetSymbolAddress((void**)&woT,   g_woT);
    cudaGetSymbolAddress((void**)&qaF,   g_qaF);
    cudaGetSymbolAddress((void**)&qaH,   g_qaH);
    cudaGetSymbolAddress((void**)&qH,    g_qH);
    cudaGetSymbolAddress((void**)&latF,  g_latF);
    cudaGetSymbolAddress((void**)&kinH,  g_kinH);
    cudaGetSymbolAddress((void**)&qinH,  g_qinH);
    cudaGetSymbolAddress((void**)&olatH, g_olatH);
    cudaGetSymbolAddress((void**)&oH,    g_oH);

    const float scale = 1.0f / sqrtf((float)(NOPE_ + ROPE_));

    // --- convert inputs / weights to fp16 (weights transposed to [N][K]) ---
    {
        int n4 = T_ * HID_ / 4;
        f2h_kernel<<<(n4 + 255) / 256, 256>>>(hidden, hH, n4);
    }
    dim3 tb(32, 8);
    t2h_kernel<<<dim3(QLORA_ / 32, HID_ / 32, 1), tb>>>(w_qa, wqaT, HID_, QLORA_, 0, 0);
    t2h_kernel<<<dim3(H_ * QDIM_ / 32, QLORA_ / 32, 1), tb>>>(w_qb, wqbT, QLORA_, H_ * QDIM_, 0, 0);
    t2h_kernel<<<dim3(DQK_ / 32, HID_ / 32, 1), tb>>>(w_kva, wkvaT, HID_, DQK_, 0, 0);
    t2h_kernel<<<dim3(HID_ / 32, H_ * VDIM_ / 32, 1), tb>>>(w_o, woT, H_ * VDIM_, HID_, 0, 0);
    t2h_kernel<<<dim3(KVLORA_ / 32, NOPE_ / 32, H_), tb>>>(w_kc, wkcT, NOPE_, KVLORA_,
                 (long)NOPE_ * KVLORA_, (long)NOPE_ * KVLORA_);
    t2h_kernel<<<dim3(VDIM_ / 32, KVLORA_ / 32, H_), tb>>>(w_vc, wvcT, KVLORA_, VDIM_,
                 (long)KVLORA_ * VDIM_, (long)KVLORA_ * VDIM_);

    // 1) qaF = hidden @ w_qa
    launch_hgemm<float>(hH, wqaT, qaF, T_, QLORA_, HID_, HID_, HID_, QLORA_, 1, 0, 0, 0, 1.f);
    // 2) qaH = rms(qaF)
    rms_kernel<__half><<<T_, 256>>>(qaF, gqa, qaH, QLORA_, QLORA_, QLORA_);
    // 3) qH = qaH @ w_qb
    launch_hgemm<__half>(qaH, wqbT, qH, T_, H_ * QDIM_, QLORA_, QLORA_, QLORA_, H_ * QDIM_, 1, 0, 0, 0, 1.f);
    // 4) latF = hidden @ w_kva
    launch_hgemm<float>(hH, wkvaT, latF, T_, DQK_, HID_, HID_, HID_, DQK_, 1, 0, 0, 0, 1.f);
    // 5) kinH[:, :256] = rms(latF[:, :256])
    rms_kernel<__half><<<T_, 256>>>(latF, gkva, kinH, KVLORA_, DQK_, DQK_);
    // 6) kinH[:, 256:288] = rope(latF[:, 256:288])
    rope_k_kernel<<<T_, 16>>>(positions, latF, kinH);
    // 7) qinH[:, h, :256] = scale * q_nope @ w_kc[h]   (batched)
    launch_hgemm<__half>(qH, wkcT, qinH, T_, KVLORA_, NOPE_,
                         H_ * QDIM_, NOPE_, H_ * DQK_,
                         H_, (long)QDIM_, (long)NOPE_ * KVLORA_, (long)DQK_, scale);
    // 8) qinH[:, h, 256:288] = scale * rope(q_pe)
    rope_q_kernel<<<T_, H_ * 16>>>(positions, qH, qinH, scale);
    // 9) flash attention -> olatH
    {
        cudaFuncSetAttribute(attn_kernel, cudaFuncAttributeMaxDynamicSharedMemorySize, ATT_SMEM);
        dim3 grid(T_ / 64, H_);
        attn_kernel<<<grid, 256, ATT_SMEM>>>(qinH, kinH, olatH);
    }
    // 10) oH[:, h*64:] = olatH[:, h, :] @ w_vc[h]   (batched)
    launch_hgemm<__half>(olatH, wvcT, oH, T_, VDIM_, KVLORA_,
                         H_ * KVLORA_, KVLORA_, H_ * VDIM_,
                         H_, (long)KVLORA_, (long)KVLORA_ * VDIM_, (long)VDIM_, 1.f);
    // 11) out = oH @ w_o
    launch_hgemm<float>(oH, woT, out, T_, HID_, H_ * VDIM_, H_ * VDIM_, H_ * VDIM_, HID_, 1, 0, 0, 0, 1.f);
}